// round 6
// baseline (speedup 1.0000x reference)
#include <cuda_runtime.h>
#include <cstdint>

#define NN 16384
#define NH 128
#define NE (NN*32)

// ---------------- device scratch ----------------
__device__ __align__(16) float g_deg[NN];
__device__ __align__(16) float g_h[NN*NH];     // x @ W
__device__ __align__(16) float g_agg[NN*NH];   // scatter accumulator
__device__ __align__(16) float g_h2[NN*NH];    // relu(gcn), tf32-rounded

#define KC 64
#define LDSW 68    // k_xw smem stride
#define KC2 32
#define LDS2 36    // k_gemm smem stride: (36r+c)%32 = (4r+c)%32 -> CF frag loads
#define TPAD 129   // transpose staging stride

__device__ __forceinline__ float tf32r(float v){
    uint32_t t; asm("cvt.rna.tf32.f32 %0, %1;" : "=r"(t) : "f"(v));
    return __uint_as_float(t);
}
__device__ __forceinline__ void cp16(float* dst, const float* src){
    uint32_t d = (uint32_t)__cvta_generic_to_shared(dst);
    asm volatile("cp.async.cg.shared.global [%0], [%1], 16;" :: "r"(d), "l"(src));
}
__device__ __forceinline__ void mma_tf32(float* d,
        uint32_t a0, uint32_t a1, uint32_t a2, uint32_t a3,
        uint32_t b0, uint32_t b1){
    asm volatile(
        "mma.sync.aligned.m16n8k8.row.col.f32.tf32.tf32.f32 "
        "{%0,%1,%2,%3}, {%4,%5,%6,%7}, {%8,%9}, {%0,%1,%2,%3};"
        : "+f"(d[0]), "+f"(d[1]), "+f"(d[2]), "+f"(d[3])
        : "r"(a0), "r"(a1), "r"(a2), "r"(a3), "r"(b0), "r"(b1));
}

// ---------------- stage 1: init ----------------
__global__ void k_init(){
    int i = blockIdx.x * blockDim.x + threadIdx.x;
    if (i < NN*NH) g_agg[i] = 0.0f;
    if (i < NN)    g_deg[i] = 1.0f;   // self-loop
}

// ---------------- stage 2: degree (edge_index is int32) ----------------
__global__ void k_degree(const int* __restrict__ ei){
    int e = blockIdx.x * blockDim.x + threadIdx.x;
    if (e >= NE) return;
    atomicAdd(&g_deg[ei[NE + e]], 1.0f);
}

// ---------------- stage 3: h = x @ W via tf32 mma ----------------
__global__ void __launch_bounds__(256, 2) k_xw(const float* __restrict__ x,
                                               const float* __restrict__ W){
    extern __shared__ float sm[];
    float* As = sm;
    float* Bs = sm + 128*LDSW;

    int tid  = threadIdx.x;
    int lane = tid & 31;
    int wid  = tid >> 5;
    int m0w  = (wid >> 2) * 64;
    int n0w  = (wid & 3) * 32;
    int row0 = blockIdx.x * 128;
    int grp  = lane >> 2, qc = lane & 3;

    float acc[4][4][4];
#pragma unroll
    for (int i = 0; i < 4; i++)
#pragma unroll
        for (int j = 0; j < 4; j++)
#pragma unroll
            for (int q = 0; q < 4; q++) acc[i][j][q] = 0.0f;

    for (int kc = 0; kc < 2; ++kc){
        if (kc) __syncthreads();
#pragma unroll
        for (int i = 0; i < 8; ++i){
            int idx = i*256 + tid;
            int r = idx >> 4, c4 = idx & 15;
            float4 v = *reinterpret_cast<const float4*>(x + (size_t)(row0 + r)*NH + kc*KC + c4*4);
            v.x = tf32r(v.x); v.y = tf32r(v.y); v.z = tf32r(v.z); v.w = tf32r(v.w);
            *reinterpret_cast<float4*>(As + r*LDSW + c4*4) = v;
        }
#pragma unroll
        for (int i = 0; i < 8; ++i){
            int idx = i*256 + tid;
            int n = idx & 127, kk4 = idx >> 7;
            float4 v;
            v.x = tf32r(W[(size_t)(kc*KC + kk4*4 + 0)*NH + n]);
            v.y = tf32r(W[(size_t)(kc*KC + kk4*4 + 1)*NH + n]);
            v.z = tf32r(W[(size_t)(kc*KC + kk4*4 + 2)*NH + n]);
            v.w = tf32r(W[(size_t)(kc*KC + kk4*4 + 3)*NH + n]);
            *reinterpret_cast<float4*>(Bs + n*LDSW + kk4*4) = v;
        }
        __syncthreads();

#pragma unroll
        for (int k8 = 0; k8 < KC/8; ++k8){
            int kb = k8*8;
            uint32_t a[4][4], b[4][2];
#pragma unroll
            for (int mf = 0; mf < 4; ++mf){
                int r0 = m0w + mf*16 + grp;
                a[mf][0] = __float_as_uint(As[r0*LDSW     + kb + qc]);
                a[mf][1] = __float_as_uint(As[(r0+8)*LDSW + kb + qc]);
                a[mf][2] = __float_as_uint(As[r0*LDSW     + kb + qc + 4]);
                a[mf][3] = __float_as_uint(As[(r0+8)*LDSW + kb + qc + 4]);
            }
#pragma unroll
            for (int nf = 0; nf < 4; ++nf){
                int rn = n0w + nf*8 + grp;
                b[nf][0] = __float_as_uint(Bs[rn*LDSW + kb + qc]);
                b[nf][1] = __float_as_uint(Bs[rn*LDSW + kb + qc + 4]);
            }
#pragma unroll
            for (int mf = 0; mf < 4; ++mf)
#pragma unroll
                for (int nf = 0; nf < 4; ++nf)
                    mma_tf32(acc[mf][nf], a[mf][0], a[mf][1], a[mf][2], a[mf][3],
                             b[nf][0], b[nf][1]);
        }
    }

#pragma unroll
    for (int mf = 0; mf < 4; ++mf)
#pragma unroll
        for (int nf = 0; nf < 4; ++nf){
            int r = m0w + mf*16 + grp;
            int c = n0w + nf*8 + 2*qc;
            *reinterpret_cast<float2*>(g_h + (size_t)(row0 + r)*NH + c) =
                make_float2(acc[mf][nf][0], acc[mf][nf][1]);
            *reinterpret_cast<float2*>(g_h + (size_t)(row0 + r + 8)*NH + c) =
                make_float2(acc[mf][nf][2], acc[mf][nf][3]);
        }
}

// ---------------- stage 4: edge scatter ----------------
__global__ void k_scatter(const int* __restrict__ ei){
    int g = blockIdx.x * blockDim.x + threadIdx.x;
    int e = g >> 5;
    if (e >= NE) return;
    int lane = g & 31;
    int r = ei[e];
    int c = ei[NE + e];
    float nrm = rsqrtf(g_deg[r] * g_deg[c]);
    float4 hv = *reinterpret_cast<const float4*>(g_h + (size_t)r*NH + lane*4);
    float4 v = make_float4(nrm*hv.x, nrm*hv.y, nrm*hv.z, nrm*hv.w);
    atomicAdd(reinterpret_cast<float4*>(g_agg + (size_t)c*NH + lane*4), v);
}

// ---------------- stage 5: self-loop + bias + relu + tf32 round -------------
__global__ void k_final(const float* __restrict__ b){
    int i = blockIdx.x * blockDim.x + threadIdx.x;
    if (i >= NN*NH) return;
    int n = i >> 7, c = i & 127;
    float v = g_agg[i] + g_h[i] / g_deg[n] + b[c];
    g_h2[i] = tf32r(v > 0.0f ? v : 0.0f);
}

// ---------------- stage 6: C = H @ H^T, upper-tri, persistent + pipelined ---
#define NTILES 8256        // 128*129/2
#define STG (2*128*LDS2)   // floats per stage (A+B)
#define GEMM_GRID 304      // 2 per SM on 152-SM GB300

__global__ void __launch_bounds__(256, 2) k_gemm(float* __restrict__ out){
    extern __shared__ float sm[];    // 3 stages x STG floats; S = stages 1..2

    int tid  = threadIdx.x;
    int lane = tid & 31;
    int wid  = tid >> 5;
    int m0w  = (wid >> 2) * 64;
    int n0w  = (wid & 3) * 32;
    int grp  = lane >> 2, qc = lane & 3;

    int lr[4], lc4[4];
#pragma unroll
    for (int i = 0; i < 4; ++i){
        int idx = i*256 + tid;
        lr[i] = idx >> 3; lc4[i] = idx & 7;
    }

#define PREFETCH_PTR(Ap, Bp, cidx, stage) do {                              \
    float* Asp = sm + (stage)*STG;                                          \
    float* Bsp = Asp + 128*LDS2;                                            \
    _Pragma("unroll")                                                       \
    for (int i = 0; i < 4; ++i){                                            \
        cp16(Asp + lr[i]*LDS2 + lc4[i]*4, (Ap) + lr[i]*NH + (cidx)*KC2 + lc4[i]*4); \
        cp16(Bsp + lr[i]*LDS2 + lc4[i]*4, (Bp) + lr[i]*NH + (cidx)*KC2 + lc4[i]*4); \
    }                                                                       \
    asm volatile("cp.async.commit_group;");                                 \
} while(0)

    // first tile: decode + prefetch chunk 0
    int tile = blockIdx.x;
    int tm = 0, rem = tile;
    while (rem >= 128 - tm){ rem -= 128 - tm; tm++; }
    int tn = tm + rem;
    const float* Ag = g_h2 + (size_t)tm * 128 * NH;
    const float* Bg = g_h2 + (size_t)tn * 128 * NH;
    PREFETCH_PTR(Ag, Bg, 0, 0);

    for (; tile < NTILES; tile += GEMM_GRID){
        __syncthreads();                    // S reads from prev tile done
        PREFETCH_PTR(Ag, Bg, 1, 1);

        float acc[4][4][4];
#pragma unroll
        for (int i = 0; i < 4; i++)
#pragma unroll
            for (int j = 0; j < 4; j++)
#pragma unroll
                for (int q = 0; q < 4; q++) acc[i][j][q] = 0.0f;

#pragma unroll
        for (int c = 0; c < 4; ++c){
            if (c < 3) asm volatile("cp.async.wait_group 1;");
            else       asm volatile("cp.async.wait_group 0;");
            __syncthreads();
            if (c + 2 < 4) PREFETCH_PTR(Ag, Bg, c + 2, (c + 2) % 3);

            float* As = sm + (c % 3)*STG;
            float* Bs = As + 128*LDS2;
#pragma unroll
            for (int k8 = 0; k8 < KC2/8; ++k8){
                int kb = k8*8;
                uint32_t a[4][4], b[4][2];
#pragma unroll
                for (int mf = 0; mf < 4; ++mf){
                    int r0 = m0w + mf*16 + grp;
                    a[mf][0] = __float_as_uint(As[r0*LDS2     + kb + qc]);
                    a[mf][1] = __float_as_uint(As[(r0+8)*LDS2 + kb + qc]);
                    a[mf][2] = __float_as_uint(As[r0*LDS2     + kb + qc + 4]);
                    a[mf][3] = __float_as_uint(As[(r0+8)*LDS2 + kb + qc + 4]);
                }
#pragma unroll
                for (int nf = 0; nf < 4; ++nf){
                    int rn = n0w + nf*8 + grp;
                    b[nf][0] = __float_as_uint(Bs[rn*LDS2 + kb + qc]);
                    b[nf][1] = __float_as_uint(Bs[rn*LDS2 + kb + qc + 4]);
                }
#pragma unroll
                for (int mf = 0; mf < 4; ++mf)
#pragma unroll
                    for (int nf = 0; nf < 4; ++nf)
                        mma_tf32(acc[mf][nf], a[mf][0], a[mf][1], a[mf][2], a[mf][3],
                                 b[nf][0], b[nf][1]);
            }
        }
        __syncthreads();                    // all reads of stage0 (chunk3) done

        // prefetch NEXT tile chunk 0 into stage 0 (overlaps epilogue writes)
        int ntile = tile + GEMM_GRID;
        int ntm = tm, nrem = 0;
        if (ntile < NTILES){
            ntm = 0; nrem = ntile;
            while (nrem >= 128 - ntm){ nrem -= 128 - ntm; ntm++; }
            const float* nAg = g_h2 + (size_t)ntm * 128 * NH;
            const float* nBg = g_h2 + (size_t)(ntm + nrem) * 128 * NH;
            PREFETCH_PTR(nAg, nBg, 0, 0);
        }

        // direct (coalesced) write of (tm, tn)
        float* outB = out + (size_t)(tm*128) * NN + (size_t)(tn*128);
#pragma unroll
        for (int mf = 0; mf < 4; ++mf)
#pragma unroll
            for (int nf = 0; nf < 4; ++nf){
                int r = m0w + mf*16 + grp;
                int c = n0w + nf*8 + 2*qc;
                *reinterpret_cast<float2*>(outB + (size_t)r*NN + c) =
                    make_float2(acc[mf][nf][0], acc[mf][nf][1]);
                *reinterpret_cast<float2*>(outB + (size_t)(r+8)*NN + c) =
                    make_float2(acc[mf][nf][2], acc[mf][nf][3]);
            }

        if (tm != tn){
            // mirrored (tn, tm): stage in S = stages 1..2 (no alias with stage0)
            float* S = sm + STG;   // 128 x TPAD = 66048 B <= 2*STG*4 = 73728 B
#pragma unroll
            for (int mf = 0; mf < 4; ++mf)
#pragma unroll
                for (int nf = 0; nf < 4; ++nf){
                    int r = m0w + mf*16 + grp;
                    int c = n0w + nf*8 + 2*qc;
                    S[r*TPAD + c]       = acc[mf][nf][0];
                    S[r*TPAD + c + 1]   = acc[mf][nf][1];
                    S[(r+8)*TPAD + c]   = acc[mf][nf][2];
                    S[(r+8)*TPAD + c+1] = acc[mf][nf][3];
                }
            __syncthreads();
            float* outT = out + (size_t)(tn*128) * NN + (size_t)(tm*128);
            for (int rr = wid; rr < 128; rr += 8){
#pragma unroll
                for (int j = 0; j < 4; ++j){
                    int c = j*32 + lane;
                    outT[(size_t)rr*NN + c] = S[c*TPAD + rr];   // CF columns
                }
            }
        }

        // advance tile decode
        tm = ntm; tn = ntm + nrem;
        Ag = g_h2 + (size_t)tm * 128 * NH;
        Bg = g_h2 + (size_t)tn * 128 * NH;
    }
#undef PREFETCH_PTR
}

// ---------------- launcher ----------------
extern "C" void kernel_launch(void* const* d_in, const int* in_sizes, int n_in,
                              void* d_out, int out_size){
    const float* x  = (const float*)d_in[0];
    const int*   ei = (const int*)d_in[1];
    const float* W  = (const float*)d_in[2];
    const float* b  = (const float*)d_in[3];
    float*       out = (float*)d_out;

    int smem_xw   = 2*128*LDSW*4;       // 69632 B
    int smem_gemm = 3*STG*4;            // 110592 B
    cudaFuncSetAttribute(k_xw,   cudaFuncAttributeMaxDynamicSharedMemorySize, smem_xw);
    cudaFuncSetAttribute(k_gemm, cudaFuncAttributeMaxDynamicSharedMemorySize, smem_gemm);

    k_init   <<<(NN*NH + 255)/256, 256>>>();
    k_degree <<<(NE + 255)/256, 256>>>(ei);
    k_xw     <<<NN/128, 256, smem_xw>>>(x, W);
    k_scatter<<<(NE*32)/256, 256>>>(ei);
    k_final  <<<(NN*NH + 255)/256, 256>>>(b);
    k_gemm   <<<GEMM_GRID, 256, smem_gemm>>>(out);
}

// round 7
// speedup vs baseline: 1.1472x; 1.1472x over previous
#include <cuda_runtime.h>
#include <cstdint>

#define NN 16384
#define NH 128
#define NE (NN*32)

// ---------------- device scratch ----------------
__device__ __align__(16) float g_deg[NN];
__device__ __align__(16) float g_h[NN*NH];     // x @ W
__device__ __align__(16) float g_h2[NN*NH];    // relu(gcn), tf32-rounded
__device__ int g_off[NN+1];                    // CSR offsets (by target)
__device__ int g_cur[NN];                      // fill cursors
__device__ int g_csr[NE];                      // edge sources grouped by target

#define KC 64
#define LDSW 68    // k_xw smem stride
#define KC2 32
#define LDS2 36    // k_gemm smem stride: (36r+c)%32 = (4r+c)%32 -> CF frag loads
#define TPAD 129   // transpose staging stride

__device__ __forceinline__ float tf32r(float v){
    uint32_t t; asm("cvt.rna.tf32.f32 %0, %1;" : "=r"(t) : "f"(v));
    return __uint_as_float(t);
}
__device__ __forceinline__ void cp16(float* dst, const float* src){
    uint32_t d = (uint32_t)__cvta_generic_to_shared(dst);
    asm volatile("cp.async.cg.shared.global [%0], [%1], 16;" :: "r"(d), "l"(src));
}
__device__ __forceinline__ void mma_tf32(float* d,
        uint32_t a0, uint32_t a1, uint32_t a2, uint32_t a3,
        uint32_t b0, uint32_t b1){
    asm volatile(
        "mma.sync.aligned.m16n8k8.row.col.f32.tf32.tf32.f32 "
        "{%0,%1,%2,%3}, {%4,%5,%6,%7}, {%8,%9}, {%0,%1,%2,%3};"
        : "+f"(d[0]), "+f"(d[1]), "+f"(d[2]), "+f"(d[3])
        : "r"(a0), "r"(a1), "r"(a2), "r"(a3), "r"(b0), "r"(b1));
}

// ---------------- stage 1: deg init ----------------
__global__ void k_init(){
    int i = blockIdx.x * blockDim.x + threadIdx.x;
    if (i < NN) g_deg[i] = 1.0f;   // self-loop
}

// ---------------- stage 2: degree (edge_index is int32) ----------------
__global__ void k_degree(const int* __restrict__ ei){
    int e = blockIdx.x * blockDim.x + threadIdx.x;
    if (e >= NE) return;
    atomicAdd(&g_deg[ei[NE + e]], 1.0f);
}

// ---------------- stage 3: CSR offsets (one CTA, Hillis-Steele) -------------
__global__ void __launch_bounds__(1024) k_scan(){
    __shared__ int ps[1024];
    int t = threadIdx.x;
    int base = t * 16;
    int c[16]; int s = 0;
#pragma unroll
    for (int i = 0; i < 16; ++i){ c[i] = (int)g_deg[base+i] - 1; s += c[i]; }
    ps[t] = s; __syncthreads();
    for (int off = 1; off < 1024; off <<= 1){
        int v = (t >= off) ? ps[t-off] : 0;
        __syncthreads();
        ps[t] += v;
        __syncthreads();
    }
    int ex = ps[t] - s;   // exclusive start of this thread's chunk
#pragma unroll
    for (int i = 0; i < 16; ++i){
        g_off[base+i] = ex; g_cur[base+i] = ex; ex += c[i];
    }
    if (t == 1023) g_off[NN] = ex;   // == NE
}

// ---------------- stage 4: CSR fill ----------------
__global__ void k_fill(const int* __restrict__ ei){
    int e = blockIdx.x * blockDim.x + threadIdx.x;
    if (e >= NE) return;
    int r = ei[e];
    int c = ei[NE + e];
    int pos = atomicAdd(&g_cur[c], 1);
    g_csr[pos] = r;
}

// ---------------- stage 5: h = x @ W via tf32 mma ----------------
__global__ void __launch_bounds__(256, 2) k_xw(const float* __restrict__ x,
                                               const float* __restrict__ W){
    extern __shared__ float sm[];
    float* As = sm;
    float* Bs = sm + 128*LDSW;

    int tid  = threadIdx.x;
    int lane = tid & 31;
    int wid  = tid >> 5;
    int m0w  = (wid >> 2) * 64;
    int n0w  = (wid & 3) * 32;
    int row0 = blockIdx.x * 128;
    int grp  = lane >> 2, qc = lane & 3;

    float acc[4][4][4];
#pragma unroll
    for (int i = 0; i < 4; i++)
#pragma unroll
        for (int j = 0; j < 4; j++)
#pragma unroll
            for (int q = 0; q < 4; q++) acc[i][j][q] = 0.0f;

    for (int kc = 0; kc < 2; ++kc){
        if (kc) __syncthreads();
#pragma unroll
        for (int i = 0; i < 8; ++i){
            int idx = i*256 + tid;
            int r = idx >> 4, c4 = idx & 15;
            float4 v = *reinterpret_cast<const float4*>(x + (size_t)(row0 + r)*NH + kc*KC + c4*4);
            v.x = tf32r(v.x); v.y = tf32r(v.y); v.z = tf32r(v.z); v.w = tf32r(v.w);
            *reinterpret_cast<float4*>(As + r*LDSW + c4*4) = v;
        }
#pragma unroll
        for (int i = 0; i < 8; ++i){
            int idx = i*256 + tid;
            int n = idx & 127, kk4 = idx >> 7;
            float4 v;
            v.x = tf32r(W[(size_t)(kc*KC + kk4*4 + 0)*NH + n]);
            v.y = tf32r(W[(size_t)(kc*KC + kk4*4 + 1)*NH + n]);
            v.z = tf32r(W[(size_t)(kc*KC + kk4*4 + 2)*NH + n]);
            v.w = tf32r(W[(size_t)(kc*KC + kk4*4 + 3)*NH + n]);
            *reinterpret_cast<float4*>(Bs + n*LDSW + kk4*4) = v;
        }
        __syncthreads();

#pragma unroll
        for (int k8 = 0; k8 < KC/8; ++k8){
            int kb = k8*8;
            uint32_t a[4][4], b[4][2];
#pragma unroll
            for (int mf = 0; mf < 4; ++mf){
                int r0 = m0w + mf*16 + grp;
                a[mf][0] = __float_as_uint(As[r0*LDSW     + kb + qc]);
                a[mf][1] = __float_as_uint(As[(r0+8)*LDSW + kb + qc]);
                a[mf][2] = __float_as_uint(As[r0*LDSW     + kb + qc + 4]);
                a[mf][3] = __float_as_uint(As[(r0+8)*LDSW + kb + qc + 4]);
            }
#pragma unroll
            for (int nf = 0; nf < 4; ++nf){
                int rn = n0w + nf*8 + grp;
                b[nf][0] = __float_as_uint(Bs[rn*LDSW + kb + qc]);
                b[nf][1] = __float_as_uint(Bs[rn*LDSW + kb + qc + 4]);
            }
#pragma unroll
            for (int mf = 0; mf < 4; ++mf)
#pragma unroll
                for (int nf = 0; nf < 4; ++nf)
                    mma_tf32(acc[mf][nf], a[mf][0], a[mf][1], a[mf][2], a[mf][3],
                             b[nf][0], b[nf][1]);
        }
    }

#pragma unroll
    for (int mf = 0; mf < 4; ++mf)
#pragma unroll
        for (int nf = 0; nf < 4; ++nf){
            int r = m0w + mf*16 + grp;
            int c = n0w + nf*8 + 2*qc;
            *reinterpret_cast<float2*>(g_h + (size_t)(row0 + r)*NH + c) =
                make_float2(acc[mf][nf][0], acc[mf][nf][1]);
            *reinterpret_cast<float2*>(g_h + (size_t)(row0 + r + 8)*NH + c) =
                make_float2(acc[mf][nf][2], acc[mf][nf][3]);
        }
}

// ---------------- stage 6: fused gather + self-loop + bias + relu -----------
// one warp per target node; lane owns 4 output columns
__global__ void k_gather(const float* __restrict__ bias){
    int warp = (blockIdx.x * blockDim.x + threadIdx.x) >> 5;
    if (warp >= NN) return;
    int lane = threadIdx.x & 31;
    int cn = warp;

    float degc = g_deg[cn];
    float dic  = rsqrtf(degc);
    int beg = g_off[cn], end = g_off[cn+1];

    const float4* hc = reinterpret_cast<const float4*>(g_h + (size_t)cn*NH) + lane;
    float4 acc = *hc;
    float inv = 1.0f / degc;
    acc.x *= inv; acc.y *= inv; acc.z *= inv; acc.w *= inv;

    for (int j = beg; j < end; j += 32){
        int myе = j + lane;
        int src = 0; float wsrc = 0.0f;
        if (myе < end){
            src  = g_csr[myе];
            wsrc = dic * rsqrtf(g_deg[src]);
        }
        int cnt = min(32, end - j);
        for (int k = 0; k < cnt; ++k){
            int   r = __shfl_sync(0xffffffffu, src,  k);
            float w = __shfl_sync(0xffffffffu, wsrc, k);
            float4 hv = *(reinterpret_cast<const float4*>(g_h + (size_t)r*NH) + lane);
            acc.x += w*hv.x; acc.y += w*hv.y; acc.z += w*hv.z; acc.w += w*hv.w;
        }
    }

    float4 bv = *(reinterpret_cast<const float4*>(bias) + lane);
    acc.x += bv.x; acc.y += bv.y; acc.z += bv.z; acc.w += bv.w;
    acc.x = tf32r(acc.x > 0.0f ? acc.x : 0.0f);
    acc.y = tf32r(acc.y > 0.0f ? acc.y : 0.0f);
    acc.z = tf32r(acc.z > 0.0f ? acc.z : 0.0f);
    acc.w = tf32r(acc.w > 0.0f ? acc.w : 0.0f);
    *(reinterpret_cast<float4*>(g_h2 + (size_t)cn*NH) + lane) = acc;
}

// ---------------- stage 7: C = H @ H^T, upper-tri, cp.async pipeline (R5) ---
#define NTILES 8256        // 128*129/2
#define STG (2*128*LDS2)   // floats per stage (A+B)

__global__ void __launch_bounds__(256, 2) k_gemm(float* __restrict__ out){
    extern __shared__ float sm[];    // 3 stages x STG floats

    int tid  = threadIdx.x;
    int lane = tid & 31;
    int wid  = tid >> 5;
    int m0w  = (wid >> 2) * 64;
    int n0w  = (wid & 3) * 32;
    int grp  = lane >> 2, qc = lane & 3;

    int tm = 0, rem = blockIdx.x;
    while (rem >= 128 - tm){ rem -= 128 - tm; tm++; }
    int tn = tm + rem;

    const float* Ag = g_h2 + (size_t)tm * 128 * NH;
    const float* Bg = g_h2 + (size_t)tn * 128 * NH;

    int lr[4], lc4[4];
#pragma unroll
    for (int i = 0; i < 4; ++i){
        int idx = i*256 + tid;
        lr[i] = idx >> 3; lc4[i] = idx & 7;
    }

#define PREFETCH(cidx, stage) do {                                         \
    float* Asp = sm + (stage)*STG;                                         \
    float* Bsp = Asp + 128*LDS2;                                           \
    _Pragma("unroll")                                                      \
    for (int i = 0; i < 4; ++i){                                           \
        cp16(Asp + lr[i]*LDS2 + lc4[i]*4, Ag + lr[i]*NH + (cidx)*KC2 + lc4[i]*4); \
        cp16(Bsp + lr[i]*LDS2 + lc4[i]*4, Bg + lr[i]*NH + (cidx)*KC2 + lc4[i]*4); \
    }                                                                      \
    asm volatile("cp.async.commit_group;");                                \
} while(0)

    float acc[4][4][4];
#pragma unroll
    for (int i = 0; i < 4; i++)
#pragma unroll
        for (int j = 0; j < 4; j++)
#pragma unroll
            for (int q = 0; q < 4; q++) acc[i][j][q] = 0.0f;

    PREFETCH(0, 0);
    PREFETCH(1, 1);

#pragma unroll
    for (int c = 0; c < 4; ++c){
        if (c < 3) asm volatile("cp.async.wait_group 1;");
        else       asm volatile("cp.async.wait_group 0;");
        __syncthreads();
        if (c + 2 < 4) PREFETCH(c + 2, (c + 2) % 3);

        float* As = sm + (c % 3)*STG;
        float* Bs = As + 128*LDS2;
#pragma unroll
        for (int k8 = 0; k8 < KC2/8; ++k8){
            int kb = k8*8;
            uint32_t a[4][4], b[4][2];
#pragma unroll
            for (int mf = 0; mf < 4; ++mf){
                int r0 = m0w + mf*16 + grp;
                a[mf][0] = __float_as_uint(As[r0*LDS2     + kb + qc]);
                a[mf][1] = __float_as_uint(As[(r0+8)*LDS2 + kb + qc]);
                a[mf][2] = __float_as_uint(As[r0*LDS2     + kb + qc + 4]);
                a[mf][3] = __float_as_uint(As[(r0+8)*LDS2 + kb + qc + 4]);
            }
#pragma unroll
            for (int nf = 0; nf < 4; ++nf){
                int rn = n0w + nf*8 + grp;
                b[nf][0] = __float_as_uint(Bs[rn*LDS2 + kb + qc]);
                b[nf][1] = __float_as_uint(Bs[rn*LDS2 + kb + qc + 4]);
            }
#pragma unroll
            for (int mf = 0; mf < 4; ++mf)
#pragma unroll
                for (int nf = 0; nf < 4; ++nf)
                    mma_tf32(acc[mf][nf], a[mf][0], a[mf][1], a[mf][2], a[mf][3],
                             b[nf][0], b[nf][1]);
        }
        __syncthreads();
    }

    float* outB = out + (size_t)(tm*128) * NN + (size_t)(tn*128);
#pragma unroll
    for (int mf = 0; mf < 4; ++mf)
#pragma unroll
        for (int nf = 0; nf < 4; ++nf){
            int r = m0w + mf*16 + grp;
            int c = n0w + nf*8 + 2*qc;
            *reinterpret_cast<float2*>(outB + (size_t)r*NN + c) =
                make_float2(acc[mf][nf][0], acc[mf][nf][1]);
            *reinterpret_cast<float2*>(outB + (size_t)(r+8)*NN + c) =
                make_float2(acc[mf][nf][2], acc[mf][nf][3]);
        }

    if (tm == tn) return;

    float* S = sm;   // 128 x TPAD floats = 66048 B <= 110592 B
#pragma unroll
    for (int mf = 0; mf < 4; ++mf)
#pragma unroll
        for (int nf = 0; nf < 4; ++nf){
            int r = m0w + mf*16 + grp;
            int c = n0w + nf*8 + 2*qc;
            S[r*TPAD + c]       = acc[mf][nf][0];
            S[r*TPAD + c + 1]   = acc[mf][nf][1];
            S[(r+8)*TPAD + c]   = acc[mf][nf][2];
            S[(r+8)*TPAD + c+1] = acc[mf][nf][3];
        }
    __syncthreads();

    float* outT = out + (size_t)(tn*128) * NN + (size_t)(tm*128);
    for (int rr = wid; rr < 128; rr += 8){
#pragma unroll
        for (int j = 0; j < 4; ++j){
            int c = j*32 + lane;
            outT[(size_t)rr*NN + c] = S[c*TPAD + rr];
        }
    }
#undef PREFETCH
}

// ---------------- launcher ----------------
extern "C" void kernel_launch(void* const* d_in, const int* in_sizes, int n_in,
                              void* d_out, int out_size){
    const float* x  = (const float*)d_in[0];
    const int*   ei = (const int*)d_in[1];
    const float* W  = (const float*)d_in[2];
    const float* b  = (const float*)d_in[3];
    float*       out = (float*)d_out;

    int smem_xw   = 2*128*LDSW*4;       // 69632 B
    int smem_gemm = 3*STG*4;            // 110592 B
    cudaFuncSetAttribute(k_xw,   cudaFuncAttributeMaxDynamicSharedMemorySize, smem_xw);
    cudaFuncSetAttribute(k_gemm, cudaFuncAttributeMaxDynamicSharedMemorySize, smem_gemm);

    k_init   <<<NN/256, 256>>>();
    k_degree <<<(NE + 255)/256, 256>>>(ei);
    k_scan   <<<1, 1024>>>();
    k_fill   <<<(NE + 255)/256, 256>>>(ei);
    k_xw     <<<NN/128, 256, smem_xw>>>(x, W);
    k_gather <<<(NN*32)/256, 256>>>(b);
    k_gemm   <<<NTILES, 256, smem_gemm>>>(out);
}

// round 8
// speedup vs baseline: 1.2952x; 1.1290x over previous
#include <cuda_runtime.h>
#include <cstdint>

#define NN 16384
#define NH 128
#define NE (NN*32)

// ---------------- device scratch ----------------
__device__ __align__(16) float g_deg[NN];
__device__ __align__(16) float g_h[NN*NH];     // x @ W
__device__ __align__(16) float g_h2[NN*NH];    // relu(gcn), tf32-rounded
__device__ int g_off[NN+1];                    // CSR offsets (by target)
__device__ int g_cur[NN];                      // fill cursors
__device__ int g_csr[NE];                      // edge sources grouped by target

#define KC 64
#define LDSW 68    // k_xw smem stride
#define KC2 32
#define LDS2 36    // k_gemm smem stride: (36r+c)%32 = (4r+c)%32 -> CF frag loads
#define TS 132     // transposed staging stride (mult of 4; CF stores & row reads)

__device__ __forceinline__ float tf32r(float v){
    uint32_t t; asm("cvt.rna.tf32.f32 %0, %1;" : "=r"(t) : "f"(v));
    return __uint_as_float(t);
}
__device__ __forceinline__ void cp16(float* dst, const float* src){
    uint32_t d = (uint32_t)__cvta_generic_to_shared(dst);
    asm volatile("cp.async.cg.shared.global [%0], [%1], 16;" :: "r"(d), "l"(src));
}
__device__ __forceinline__ void mma_tf32(float* d,
        uint32_t a0, uint32_t a1, uint32_t a2, uint32_t a3,
        uint32_t b0, uint32_t b1){
    asm volatile(
        "mma.sync.aligned.m16n8k8.row.col.f32.tf32.tf32.f32 "
        "{%0,%1,%2,%3}, {%4,%5,%6,%7}, {%8,%9}, {%0,%1,%2,%3};"
        : "+f"(d[0]), "+f"(d[1]), "+f"(d[2]), "+f"(d[3])
        : "r"(a0), "r"(a1), "r"(a2), "r"(a3), "r"(b0), "r"(b1));
}

// ---------------- stage 1: deg init ----------------
__global__ void k_init(){
    int i = blockIdx.x * blockDim.x + threadIdx.x;
    if (i < NN) g_deg[i] = 1.0f;   // self-loop
}

// ---------------- stage 2: degree (edge_index is int32) ----------------
__global__ void k_degree(const int* __restrict__ ei){
    int e = blockIdx.x * blockDim.x + threadIdx.x;
    if (e >= NE) return;
    atomicAdd(&g_deg[ei[NE + e]], 1.0f);
}

// ---------------- stage 3: CSR offsets (one CTA, Hillis-Steele) -------------
__global__ void __launch_bounds__(1024) k_scan(){
    __shared__ int ps[1024];
    int t = threadIdx.x;
    int base = t * 16;
    int c[16]; int s = 0;
#pragma unroll
    for (int i = 0; i < 16; ++i){ c[i] = (int)g_deg[base+i] - 1; s += c[i]; }
    ps[t] = s; __syncthreads();
    for (int off = 1; off < 1024; off <<= 1){
        int v = (t >= off) ? ps[t-off] : 0;
        __syncthreads();
        ps[t] += v;
        __syncthreads();
    }
    int ex = ps[t] - s;
#pragma unroll
    for (int i = 0; i < 16; ++i){
        g_off[base+i] = ex; g_cur[base+i] = ex; ex += c[i];
    }
    if (t == 1023) g_off[NN] = ex;
}

// ---------------- stage 4: CSR fill ----------------
__global__ void k_fill(const int* __restrict__ ei){
    int e = blockIdx.x * blockDim.x + threadIdx.x;
    if (e >= NE) return;
    int r = ei[e];
    int c = ei[NE + e];
    int pos = atomicAdd(&g_cur[c], 1);
    g_csr[pos] = r;
}

// ---------------- stage 5: h = x @ W via tf32 mma ----------------
__global__ void __launch_bounds__(256, 2) k_xw(const float* __restrict__ x,
                                               const float* __restrict__ W){
    extern __shared__ float sm[];
    float* As = sm;
    float* Bs = sm + 128*LDSW;

    int tid  = threadIdx.x;
    int lane = tid & 31;
    int wid  = tid >> 5;
    int m0w  = (wid >> 2) * 64;
    int n0w  = (wid & 3) * 32;
    int row0 = blockIdx.x * 128;
    int grp  = lane >> 2, qc = lane & 3;

    float acc[4][4][4];
#pragma unroll
    for (int i = 0; i < 4; i++)
#pragma unroll
        for (int j = 0; j < 4; j++)
#pragma unroll
            for (int q = 0; q < 4; q++) acc[i][j][q] = 0.0f;

    for (int kc = 0; kc < 2; ++kc){
        if (kc) __syncthreads();
#pragma unroll
        for (int i = 0; i < 8; ++i){
            int idx = i*256 + tid;
            int r = idx >> 4, c4 = idx & 15;
            float4 v = *reinterpret_cast<const float4*>(x + (size_t)(row0 + r)*NH + kc*KC + c4*4);
            v.x = tf32r(v.x); v.y = tf32r(v.y); v.z = tf32r(v.z); v.w = tf32r(v.w);
            *reinterpret_cast<float4*>(As + r*LDSW + c4*4) = v;
        }
#pragma unroll
        for (int i = 0; i < 8; ++i){
            int idx = i*256 + tid;
            int n = idx & 127, kk4 = idx >> 7;
            float4 v;
            v.x = tf32r(W[(size_t)(kc*KC + kk4*4 + 0)*NH + n]);
            v.y = tf32r(W[(size_t)(kc*KC + kk4*4 + 1)*NH + n]);
            v.z = tf32r(W[(size_t)(kc*KC + kk4*4 + 2)*NH + n]);
            v.w = tf32r(W[(size_t)(kc*KC + kk4*4 + 3)*NH + n]);
            *reinterpret_cast<float4*>(Bs + n*LDSW + kk4*4) = v;
        }
        __syncthreads();

#pragma unroll
        for (int k8 = 0; k8 < KC/8; ++k8){
            int kb = k8*8;
            uint32_t a[4][4], b[4][2];
#pragma unroll
            for (int mf = 0; mf < 4; ++mf){
                int r0 = m0w + mf*16 + grp;
                a[mf][0] = __float_as_uint(As[r0*LDSW     + kb + qc]);
                a[mf][1] = __float_as_uint(As[(r0+8)*LDSW + kb + qc]);
                a[mf][2] = __float_as_uint(As[r0*LDSW     + kb + qc + 4]);
                a[mf][3] = __float_as_uint(As[(r0+8)*LDSW + kb + qc + 4]);
            }
#pragma unroll
            for (int nf = 0; nf < 4; ++nf){
                int rn = n0w + nf*8 + grp;
                b[nf][0] = __float_as_uint(Bs[rn*LDSW + kb + qc]);
                b[nf][1] = __float_as_uint(Bs[rn*LDSW + kb + qc + 4]);
            }
#pragma unroll
            for (int mf = 0; mf < 4; ++mf)
#pragma unroll
                for (int nf = 0; nf < 4; ++nf)
                    mma_tf32(acc[mf][nf], a[mf][0], a[mf][1], a[mf][2], a[mf][3],
                             b[nf][0], b[nf][1]);
        }
    }

#pragma unroll
    for (int mf = 0; mf < 4; ++mf)
#pragma unroll
        for (int nf = 0; nf < 4; ++nf){
            int r = m0w + mf*16 + grp;
            int c = n0w + nf*8 + 2*qc;
            *reinterpret_cast<float2*>(g_h + (size_t)(row0 + r)*NH + c) =
                make_float2(acc[mf][nf][0], acc[mf][nf][1]);
            *reinterpret_cast<float2*>(g_h + (size_t)(row0 + r + 8)*NH + c) =
                make_float2(acc[mf][nf][2], acc[mf][nf][3]);
        }
}

// ---------------- stage 6: fused gather + self-loop + bias + relu -----------
__global__ void k_gather(const float* __restrict__ bias){
    int warp = (blockIdx.x * blockDim.x + threadIdx.x) >> 5;
    if (warp >= NN) return;
    int lane = threadIdx.x & 31;
    int cn = warp;

    float degc = g_deg[cn];
    float dic  = rsqrtf(degc);
    int beg = g_off[cn], end = g_off[cn+1];

    const float4* hc = reinterpret_cast<const float4*>(g_h + (size_t)cn*NH) + lane;
    float4 acc = *hc;
    float inv = 1.0f / degc;
    acc.x *= inv; acc.y *= inv; acc.z *= inv; acc.w *= inv;

    for (int j = beg; j < end; j += 32){
        int me = j + lane;
        int src = 0; float wsrc = 0.0f;
        if (me < end){
            src  = g_csr[me];
            wsrc = dic * rsqrtf(g_deg[src]);
        }
        int cnt = min(32, end - j);
        for (int k = 0; k < cnt; ++k){
            int   r = __shfl_sync(0xffffffffu, src,  k);
            float w = __shfl_sync(0xffffffffu, wsrc, k);
            float4 hv = *(reinterpret_cast<const float4*>(g_h + (size_t)r*NH) + lane);
            acc.x += w*hv.x; acc.y += w*hv.y; acc.z += w*hv.z; acc.w += w*hv.w;
        }
    }

    float4 bv = *(reinterpret_cast<const float4*>(bias) + lane);
    acc.x += bv.x; acc.y += bv.y; acc.z += bv.z; acc.w += bv.w;
    acc.x = tf32r(acc.x > 0.0f ? acc.x : 0.0f);
    acc.y = tf32r(acc.y > 0.0f ? acc.y : 0.0f);
    acc.z = tf32r(acc.z > 0.0f ? acc.z : 0.0f);
    acc.w = tf32r(acc.w > 0.0f ? acc.w : 0.0f);
    *(reinterpret_cast<float4*>(g_h2 + (size_t)cn*NH) + lane) = acc;
}

// ---------------- stage 7: C = H @ H^T, upper-tri, cp.async pipeline --------
#define NTILES 8256        // 128*129/2
#define STG (2*128*LDS2)   // floats per stage (A+B)

__global__ void __launch_bounds__(256, 2) k_gemm(float* __restrict__ out){
    extern __shared__ float sm[];    // 3 stages x STG floats; S_T overlays them

    int tid  = threadIdx.x;
    int lane = tid & 31;
    int wid  = tid >> 5;
    int m0w  = (wid >> 2) * 64;
    int n0w  = (wid & 3) * 32;
    int grp  = lane >> 2, qc = lane & 3;

    int tm = 0, rem = blockIdx.x;
    while (rem >= 128 - tm){ rem -= 128 - tm; tm++; }
    int tn = tm + rem;

    const float* Ag = g_h2 + (size_t)tm * 128 * NH;
    const float* Bg = g_h2 + (size_t)tn * 128 * NH;

    int lr[4], lc4[4];
#pragma unroll
    for (int i = 0; i < 4; ++i){
        int idx = i*256 + tid;
        lr[i] = idx >> 3; lc4[i] = idx & 7;
    }

#define PREFETCH(cidx, stage) do {                                         \
    float* Asp = sm + (stage)*STG;                                         \
    float* Bsp = Asp + 128*LDS2;                                           \
    _Pragma("unroll")                                                      \
    for (int i = 0; i < 4; ++i){                                           \
        cp16(Asp + lr[i]*LDS2 + lc4[i]*4, Ag + lr[i]*NH + (cidx)*KC2 + lc4[i]*4); \
        cp16(Bsp + lr[i]*LDS2 + lc4[i]*4, Bg + lr[i]*NH + (cidx)*KC2 + lc4[i]*4); \
    }                                                                      \
    asm volatile("cp.async.commit_group;");                                \
} while(0)

    float acc[4][4][4];
#pragma unroll
    for (int i = 0; i < 4; i++)
#pragma unroll
        for (int j = 0; j < 4; j++)
#pragma unroll
            for (int q = 0; q < 4; q++) acc[i][j][q] = 0.0f;

    PREFETCH(0, 0);
    PREFETCH(1, 1);

#pragma unroll
    for (int c = 0; c < 4; ++c){
        if (c < 3) asm volatile("cp.async.wait_group 1;");
        else       asm volatile("cp.async.wait_group 0;");
        __syncthreads();             // data visible + prev-iter readers done
        if (c + 2 < 4) PREFETCH(c + 2, (c + 2) % 3);

        float* As = sm + (c % 3)*STG;
        float* Bs = As + 128*LDS2;
#pragma unroll
        for (int k8 = 0; k8 < KC2/8; ++k8){
            int kb = k8*8;
            uint32_t a[4][4], b[4][2];
#pragma unroll
            for (int mf = 0; mf < 4; ++mf){
                int r0 = m0w + mf*16 + grp;
                a[mf][0] = __float_as_uint(As[r0*LDS2     + kb + qc]);
                a[mf][1] = __float_as_uint(As[(r0+8)*LDS2 + kb + qc]);
                a[mf][2] = __float_as_uint(As[r0*LDS2     + kb + qc + 4]);
                a[mf][3] = __float_as_uint(As[(r0+8)*LDS2 + kb + qc + 4]);
            }
#pragma unroll
            for (int nf = 0; nf < 4; ++nf){
                int rn = n0w + nf*8 + grp;
                b[nf][0] = __float_as_uint(Bs[rn*LDS2 + kb + qc]);
                b[nf][1] = __float_as_uint(Bs[rn*LDS2 + kb + qc + 4]);
            }
#pragma unroll
            for (int mf = 0; mf < 4; ++mf)
#pragma unroll
                for (int nf = 0; nf < 4; ++nf)
                    mma_tf32(acc[mf][nf], a[mf][0], a[mf][1], a[mf][2], a[mf][3],
                             b[nf][0], b[nf][1]);
        }
        // no trailing __syncthreads: top-of-loop barrier orders stage reuse
    }

    // direct (coalesced) write of (tm, tn) — straight from registers
    float* outB = out + (size_t)(tm*128) * NN + (size_t)(tn*128);
#pragma unroll
    for (int mf = 0; mf < 4; ++mf)
#pragma unroll
        for (int nf = 0; nf < 4; ++nf){
            int r = m0w + mf*16 + grp;
            int c = n0w + nf*8 + 2*qc;
            *reinterpret_cast<float2*>(outB + (size_t)r*NN + c) =
                make_float2(acc[mf][nf][0], acc[mf][nf][1]);
            *reinterpret_cast<float2*>(outB + (size_t)(r+8)*NN + c) =
                make_float2(acc[mf][nf][2], acc[mf][nf][3]);
        }

    if (tm == tn) return;

    // mirrored (tn, tm): store accumulators TRANSPOSED into S_T, then write
    // whole rows with LDS.128 + STG.128 (128B coalesced).
    __syncthreads();                 // mainloop smem reads done before overlay
    float* S = sm;                   // S_T: 128 x TS floats = 67584 B
#pragma unroll
    for (int mf = 0; mf < 4; ++mf)
#pragma unroll
        for (int nf = 0; nf < 4; ++nf){
            int r = m0w + mf*16 + grp;
            int c = n0w + nf*8 + 2*qc;
            // banks: (4c + r) %32 = (8qc + grp + const)%32 -> bijective, CF
            S[c*TS + r]         = acc[mf][nf][0];
            S[(c+1)*TS + r]     = acc[mf][nf][1];
            S[c*TS + r + 8]     = acc[mf][nf][2];
            S[(c+1)*TS + r + 8] = acc[mf][nf][3];
        }
    __syncthreads();

    float* outT = out + (size_t)(tn*128) * NN + (size_t)(tm*128);
    for (int j = wid; j < 128; j += 8){
        float4 v = *reinterpret_cast<const float4*>(S + j*TS + 4*lane);
        *reinterpret_cast<float4*>(outT + (size_t)j*NN + 4*lane) = v;
    }
#undef PREFETCH
}

// ---------------- launcher ----------------
extern "C" void kernel_launch(void* const* d_in, const int* in_sizes, int n_in,
                              void* d_out, int out_size){
    const float* x  = (const float*)d_in[0];
    const int*   ei = (const int*)d_in[1];
    const float* W  = (const float*)d_in[2];
    const float* b  = (const float*)d_in[3];
    float*       out = (float*)d_out;

    int smem_xw   = 2*128*LDSW*4;       // 69632 B
    int smem_gemm = 3*STG*4;            // 110592 B (>= 128*TS*4 = 67584 B)
    cudaFuncSetAttribute(k_xw,   cudaFuncAttributeMaxDynamicSharedMemorySize, smem_xw);
    cudaFuncSetAttribute(k_gemm, cudaFuncAttributeMaxDynamicSharedMemorySize, smem_gemm);

    k_init   <<<NN/256, 256>>>();
    k_degree <<<(NE + 255)/256, 256>>>(ei);
    k_scan   <<<1, 1024>>>();
    k_fill   <<<(NE + 255)/256, 256>>>(ei);
    k_xw     <<<NN/128, 256, smem_xw>>>(x, W);
    k_gather <<<(NN*32)/256, 256>>>(b);
    k_gemm   <<<NTILES, 256, smem_gemm>>>(out);
}